// round 5
// baseline (speedup 1.0000x reference)
#include <cuda_runtime.h>
#include <cuda_bf16.h>

// Problem constants: B=8, C=64, H=W=128, G=2, D=32, K=9, OS=2.0
#define PB 16384
#define NB 8
#define NROWS (NB * PB)

__device__ float g_value[NB * PB * 64];   // (b,p,64)
__device__ float g_om[NB * PB * 54];      // (b,p,54)

// XOR swizzle: rows stride 64 floats, swizzle k by row to decollide banks.
#define SW(r) (((r) & 7) << 2)

__device__ __forceinline__ unsigned f2tf(float f) {
    unsigned r; asm("cvt.rna.tf32.f32 %0, %1;" : "=r"(r) : "f"(f)); return r;
}
__device__ __forceinline__ void split_tf(float f, unsigned& hi, unsigned& lo) {
    hi = f2tf(f);
    lo = f2tf(f - __uint_as_float(hi));
}
__device__ __forceinline__ void mma8(float* c, unsigned a0, unsigned a1,
                                     unsigned a2, unsigned a3,
                                     unsigned b0, unsigned b1) {
    asm("mma.sync.aligned.m16n8k8.row.col.f32.tf32.tf32.f32 "
        "{%0,%1,%2,%3},{%4,%5,%6,%7},{%8,%9},{%0,%1,%2,%3};"
        : "+f"(c[0]), "+f"(c[1]), "+f"(c[2]), "+f"(c[3])
        : "r"(a0), "r"(a1), "r"(a2), "r"(a3), "r"(b0), "r"(b1));
}

// ---------------------------------------------------------------------------
// K1: value projection via 3xTF32 mma (unchanged from round 4; 38us known).
// ---------------------------------------------------------------------------
__global__ void __launch_bounds__(256) k1_valproj(const float* __restrict__ x,
                                                  const float* __restrict__ vp_w,
                                                  const float* __restrict__ vp_b) {
    __shared__ unsigned Bh[4096], Bl[4096];   // [n][k] swizzled
    int t = threadIdx.x;
    for (int i = t; i < 4096; i += 256) {
        int n = i >> 6, k = i & 63;
        unsigned h, l; split_tf(vp_w[i], h, l);
        int idx = n * 64 + (k ^ SW(n));
        Bh[idx] = h; Bl[idx] = l;
    }
    __syncthreads();

    int w = t >> 5, lane = t & 31;
    int r = lane >> 2, q = lane & 3;
    size_t row0 = (size_t)blockIdx.x * 128 + w * 16;
    const float* ar = x + (row0 + r) * 64;

    float acc[8][4];
#pragma unroll
    for (int nt = 0; nt < 8; nt++)
#pragma unroll
        for (int i = 0; i < 4; i++) acc[nt][i] = 0.f;

#pragma unroll
    for (int kc = 0; kc < 8; kc++) {
        int k = kc * 8 + q;
        float a0f = __ldg(ar + k);
        float a1f = __ldg(ar + 512 + k);
        float a2f = __ldg(ar + k + 4);
        float a3f = __ldg(ar + 512 + k + 4);
        unsigned ah0, ah1, ah2, ah3, al0, al1, al2, al3;
        split_tf(a0f, ah0, al0); split_tf(a1f, ah1, al1);
        split_tf(a2f, ah2, al2); split_tf(a3f, ah3, al3);
#pragma unroll
        for (int nt = 0; nt < 8; nt++) {
            int n0 = nt * 8 + r;
            int base = n0 * 64, s = SW(n0);
            unsigned bh0 = Bh[base + (k ^ s)];
            unsigned bh1 = Bh[base + ((k + 4) ^ s)];
            unsigned bl0 = Bl[base + (k ^ s)];
            unsigned bl1 = Bl[base + ((k + 4) ^ s)];
            mma8(acc[nt], ah0, ah1, ah2, ah3, bh0, bh1);
            mma8(acc[nt], ah0, ah1, ah2, ah3, bl0, bl1);
            mma8(acc[nt], al0, al1, al2, al3, bh0, bh1);
        }
    }
#pragma unroll
    for (int nt = 0; nt < 8; nt++) {
        int jc = nt * 8 + 2 * q;
        float2 b2 = __ldg((const float2*)(vp_b + jc));
        *(float2*)&g_value[(row0 + r) * 64 + jc] =
            make_float2(acc[nt][0] + b2.x, acc[nt][1] + b2.y);
        *(float2*)&g_value[(row0 + r + 8) * 64 + jc] =
            make_float2(acc[nt][2] + b2.x, acc[nt][3] + b2.y);
    }
}

// ---------------------------------------------------------------------------
// K2: depthwise 3x3 conv (sliding window) + om GEMM via 3xTF32 mma.
// Conv output PRE-SPLIT to tf32 hi/lo in smem -> GEMM is pure LDS+mma.
// Dynamic smem 64KB: Bh | Bl | dh | dl (4096 words each).
// ---------------------------------------------------------------------------
extern __shared__ unsigned s_dyn[];

__global__ void __launch_bounds__(256) k2_dwom(const float* __restrict__ x,
                                               const float* __restrict__ dw_w,
                                               const float* __restrict__ dw_b,
                                               const float* __restrict__ om_w,
                                               const float* __restrict__ om_b) {
    unsigned* Bh = s_dyn;
    unsigned* Bl = s_dyn + 4096;
    unsigned* dh = s_dyn + 8192;
    unsigned* dl = s_dyn + 12288;
    int t = threadIdx.x;
    for (int i = t; i < 4096; i += 256) {
        int n = i >> 6, k = i & 63;
        float wv = (n < 54) ? om_w[n * 64 + k] : 0.f;
        unsigned h, l; split_tf(wv, h, l);
        int idx = n * 64 + (k ^ SW(n));
        Bh[idx] = h; Bl[idx] = l;
    }

    int bb = blockIdx.x >> 8;
    int p0 = (blockIdx.x & 255) * 64;
    int h = p0 >> 7;
    int w0 = p0 & 127;
    const float* xb = x + (size_t)bb * (PB * 64);

    // Phase A: conv, sliding window. thread = (channel c, pixel group pg).
    {
        int c = t & 63;
        int pg = t >> 6;
        float wk[9];
#pragma unroll
        for (int k = 0; k < 9; k++) wk[k] = dw_w[c * 9 + k];
        float bias = dw_b[c];
        int wstart = w0 + pg * 16;
        const float* xc = xb + c;
        float v[3][3];
#pragma unroll
        for (int ky = 0; ky < 3; ky++) {
            int yy = h + ky - 1;
            bool yok = (unsigned)yy < 128u;
            int xm1 = wstart - 1;
            v[ky][1] = (yok && (unsigned)xm1 < 128u)
                           ? __ldg(xc + ((size_t)((yy << 7) + xm1) << 6)) : 0.f;
            v[ky][2] = yok ? __ldg(xc + ((size_t)((yy << 7) + wstart) << 6)) : 0.f;
        }
        for (int i = 0; i < 16; i++) {
            int w = wstart + i;
            int xp1 = w + 1;
#pragma unroll
            for (int ky = 0; ky < 3; ky++) {
                int yy = h + ky - 1;
                v[ky][0] = v[ky][1];
                v[ky][1] = v[ky][2];
                v[ky][2] = ((unsigned)yy < 128u && (unsigned)xp1 < 128u)
                               ? __ldg(xc + ((size_t)((yy << 7) + xp1) << 6)) : 0.f;
            }
            float acc = bias;
#pragma unroll
            for (int ky = 0; ky < 3; ky++)
#pragma unroll
                for (int kx = 0; kx < 3; kx++)
                    acc = fmaf(v[ky][kx], wk[ky * 3 + kx], acc);
            int px = pg * 16 + i;
            unsigned hh_, ll_; split_tf(acc, hh_, ll_);
            int idx = px * 64 + (c ^ SW(px));
            dh[idx] = hh_; dl[idx] = ll_;
        }
    }
    __syncthreads();

    // Phase B: om GEMM via mma. warp w -> n-tile w (w<7). 4 m-tiles of 16 px.
    int w = t >> 5;
    if (w < 7) {
        int lane = t & 31;
        int r = lane >> 2, q = lane & 3;
        float acc[4][4];
#pragma unroll
        for (int mt = 0; mt < 4; mt++)
#pragma unroll
            for (int i = 0; i < 4; i++) acc[mt][i] = 0.f;
        int n0 = w * 8 + r;
        int nbase = n0 * 64, ns = SW(n0);
#pragma unroll
        for (int kc = 0; kc < 8; kc++) {
            int k = kc * 8 + q;
            unsigned bh0 = Bh[nbase + (k ^ ns)];
            unsigned bh1 = Bh[nbase + ((k + 4) ^ ns)];
            unsigned bl0 = Bl[nbase + (k ^ ns)];
            unsigned bl1 = Bl[nbase + ((k + 4) ^ ns)];
#pragma unroll
            for (int mt = 0; mt < 4; mt++) {
                int rA = mt * 16 + r, rB = rA + 8;
                int iA0 = rA * 64 + (k ^ SW(rA));
                int iB0 = rB * 64 + (k ^ SW(rB));
                int iA1 = rA * 64 + ((k + 4) ^ SW(rA));
                int iB1 = rB * 64 + ((k + 4) ^ SW(rB));
                unsigned ah0 = dh[iA0], ah1 = dh[iB0];
                unsigned ah2 = dh[iA1], ah3 = dh[iB1];
                unsigned al0 = dl[iA0], al1 = dl[iB0];
                unsigned al2 = dl[iA1], al3 = dl[iB1];
                mma8(acc[mt], ah0, ah1, ah2, ah3, bh0, bh1);
                mma8(acc[mt], ah0, ah1, ah2, ah3, bl0, bl1);
                mma8(acc[mt], al0, al1, al2, al3, bh0, bh1);
            }
        }
        int jc = w * 8 + 2 * q;
        if (jc < 54) {
            float2 ob2 = __ldg((const float2*)(om_b + jc));
#pragma unroll
            for (int mt = 0; mt < 4; mt++) {
                int pxA = p0 + mt * 16 + r;
                size_t baseA = ((size_t)bb * PB + pxA) * 54;
                *(float2*)&g_om[baseA + jc] =
                    make_float2(acc[mt][0] + ob2.x, acc[mt][1] + ob2.y);
                *(float2*)&g_om[baseA + 54 * 8 + jc] =
                    make_float2(acc[mt][2] + ob2.x, acc[mt][3] + ob2.y);
            }
        }
    }
}

// ---------------------------------------------------------------------------
// K3: DCN bilinear gather + op GEMM (3xTF32 mma) + in-register pair fold +
// BN + ReLU. Gather output PRE-SPLIT to tf32 hi/lo in smem.
// Dynamic smem: Bh(4096) | Bl(4096) | ch(2048) | cl(2048) | oms(1728) words.
// Block = 32 local pixels: p0..p0+15 and p0+8192..p0+8207.
// ---------------------------------------------------------------------------
__global__ void __launch_bounds__(256) k3_dcn(const float* __restrict__ op_w,
                                              const float* __restrict__ op_b,
                                              const float* __restrict__ bn_g,
                                              const float* __restrict__ bn_b,
                                              const float* __restrict__ bn_m,
                                              const float* __restrict__ bn_v,
                                              float* __restrict__ out) {
    unsigned* Bh = s_dyn;
    unsigned* Bl = s_dyn + 4096;
    unsigned* ch = s_dyn + 8192;
    unsigned* cl = s_dyn + 10240;
    float* oms = (float*)(s_dyn + 12288);   // [32][54]
    int t = threadIdx.x;
    for (int i = t; i < 4096; i += 256) {
        int n = i >> 6, k = i & 63;
        unsigned h, l; split_tf(op_w[i], h, l);
        int idx = n * 64 + (k ^ SW(n));
        Bh[idx] = h; Bl[idx] = l;
    }

    int bb = blockIdx.x >> 9;
    int p0 = (blockIdx.x & 511) * 16;       // in [0, 8192)

    for (int i = t; i < 32 * 54; i += 256) {
        int pl = i / 54;
        int j = i - pl * 54;
        int p = p0 + ((pl < 16) ? pl : (pl - 16 + 8192));
        oms[pl * 54 + j] = g_om[((size_t)bb * PB + p) * 54 + j];
    }
    __syncthreads();

    // Gather: 16 lanes per pixel (4 channels each), 2 passes over 32 px.
    {
        int sub = t & 15;
        int g = sub >> 3;
        int d0 = (sub & 7) * 4;
        int plh = t >> 4;
        int cb = g * 32 + d0;
        const float* vb = g_value + (size_t)bb * (PB * 64) + cb;
#pragma unroll
        for (int pass = 0; pass < 2; pass++) {
            int pl = plh + pass * 16;
            int p = p0 + plh + pass * 8192;
            int h = p >> 7;
            int w = p & 127;
            const float* omp = &oms[pl * 54 + g * 27];
            float a0 = 0.f, a1 = 0.f, a2 = 0.f, a3 = 0.f;
#pragma unroll
            for (int k = 0; k < 9; k++) {
                float ox = omp[2 * k], oy = omp[2 * k + 1], m = omp[18 + k];
                float ix = (float)w + ((float)(k - (k / 3) * 3) - 1.0f + ox) * 2.0f;
                float iy = (float)h + ((float)(k / 3) - 1.0f + oy) * 2.0f;
                float xf = floorf(ix), yf = floorf(iy);
                float tx = ix - xf, ty = iy - yf;
                int x0 = (int)xf, y0 = (int)yf;
                float wx0 = 1.f - tx, wy0 = 1.f - ty;
#pragma unroll
                for (int cr = 0; cr < 4; cr++) {
                    int dy = cr >> 1, dx = cr & 1;
                    int xc = x0 + dx, yc = y0 + dy;
                    if ((unsigned)xc < 128u && (unsigned)yc < 128u) {
                        float wgt = (dy ? ty : wy0) * (dx ? tx : wx0) * m;
                        float4 v = __ldg((const float4*)(vb + ((size_t)((yc << 7) + xc) << 6)));
                        a0 = fmaf(wgt, v.x, a0);
                        a1 = fmaf(wgt, v.y, a1);
                        a2 = fmaf(wgt, v.z, a2);
                        a3 = fmaf(wgt, v.w, a3);
                    }
                }
            }
            uint4 vh, vl;
            split_tf(a0, vh.x, vl.x); split_tf(a1, vh.y, vl.y);
            split_tf(a2, vh.z, vl.z); split_tf(a3, vh.w, vl.w);
            int idx = pl * 64 + (cb ^ SW(pl));
            *(uint4*)&ch[idx] = vh;
            *(uint4*)&cl[idx] = vl;
        }
    }
    __syncthreads();

    // op GEMM via mma: warp w -> n-tile w; m-tiles rows 0-15 (A) and 16-31 (B).
    {
        int w = t >> 5, lane = t & 31;
        int r = lane >> 2, q = lane & 3;
        float accA[4] = {0.f, 0.f, 0.f, 0.f};
        float accB[4] = {0.f, 0.f, 0.f, 0.f};
        int n0 = w * 8 + r;
        int nbase = n0 * 64, ns = SW(n0);
#pragma unroll
        for (int kc = 0; kc < 8; kc++) {
            int k = kc * 8 + q;
            unsigned bh0 = Bh[nbase + (k ^ ns)];
            unsigned bh1 = Bh[nbase + ((k + 4) ^ ns)];
            unsigned bl0 = Bl[nbase + (k ^ ns)];
            unsigned bl1 = Bl[nbase + ((k + 4) ^ ns)];
            // m-tile 0: rows r, r+8
            {
                int rA = r, rB = r + 8;
                int iA0 = rA * 64 + (k ^ SW(rA));
                int iB0 = rB * 64 + (k ^ SW(rB));
                int iA1 = rA * 64 + ((k + 4) ^ SW(rA));
                int iB1 = rB * 64 + ((k + 4) ^ SW(rB));
                unsigned ah0 = ch[iA0], ah1 = ch[iB0];
                unsigned ah2 = ch[iA1], ah3 = ch[iB1];
                unsigned al0 = cl[iA0], al1 = cl[iB0];
                unsigned al2 = cl[iA1], al3 = cl[iB1];
                mma8(accA, ah0, ah1, ah2, ah3, bh0, bh1);
                mma8(accA, ah0, ah1, ah2, ah3, bl0, bl1);
                mma8(accA, al0, al1, al2, al3, bh0, bh1);
            }
            // m-tile 1: rows 16+r, 24+r
            {
                int rA = 16 + r, rB = 24 + r;
                int iA0 = rA * 64 + (k ^ SW(rA));
                int iB0 = rB * 64 + (k ^ SW(rB));
                int iA1 = rA * 64 + ((k + 4) ^ SW(rA));
                int iB1 = rB * 64 + ((k + 4) ^ SW(rB));
                unsigned ah0 = ch[iA0], ah1 = ch[iB0];
                unsigned ah2 = ch[iA1], ah3 = ch[iB1];
                unsigned al0 = cl[iA0], al1 = cl[iB0];
                unsigned al2 = cl[iA1], al3 = cl[iB1];
                mma8(accB, ah0, ah1, ah2, ah3, bh0, bh1);
                mma8(accB, ah0, ah1, ah2, ah3, bl0, bl1);
                mma8(accB, al0, al1, al2, al3, bh0, bh1);
            }
        }
        // Fold (row r of mt0 pairs with row r of mt1), BN, ReLU, store.
        int jc = w * 8 + 2 * q;
        float2 ob2 = __ldg((const float2*)(op_b + jc));
        int cz = p0 >> 8;
        float sA = __ldg(bn_g + cz) * rsqrtf(__ldg(bn_v + cz) + 1e-5f);
        float sB = fmaf(-sA, __ldg(bn_m + cz), __ldg(bn_b + cz));
#pragma unroll
        for (int half = 0; half < 2; half++) {
            int rr = r + half * 8;
            int i0 = half * 2, i1 = half * 2 + 1;
            int p = p0 + rr;
            float z0 = fmaf(0.5f * (accA[i0] + accB[i0]) + ob2.x, sA, sB);
            float z1 = fmaf(0.5f * (accA[i1] + accB[i1]) + ob2.y, sA, sB);
            int hh = (p >> 1) & 127;
            int qq = p & 1;
            size_t base = (((size_t)bb * 32 + cz) * 128 + hh) * 128 + (qq << 6);
            *(float2*)&out[base + jc] =
                make_float2(fmaxf(z0, 0.f), fmaxf(z1, 0.f));
        }
    }
}

// ---------------------------------------------------------------------------
extern "C" void kernel_launch(void* const* d_in, const int* in_sizes, int n_in,
                              void* d_out, int out_size) {
    const float* x    = (const float*)d_in[0];
    const float* vp_w = (const float*)d_in[1];
    const float* vp_b = (const float*)d_in[2];
    const float* dw_w = (const float*)d_in[3];
    const float* dw_b = (const float*)d_in[4];
    const float* om_w = (const float*)d_in[5];
    const float* om_b = (const float*)d_in[6];
    const float* op_w = (const float*)d_in[7];
    const float* op_b = (const float*)d_in[8];
    const float* bn_g = (const float*)d_in[9];
    const float* bn_b = (const float*)d_in[10];
    const float* bn_m = (const float*)d_in[11];
    const float* bn_v = (const float*)d_in[12];
    float* out = (float*)d_out;

    const int K2_SMEM = 16384 * 4;            // 64 KB
    const int K3_SMEM = 14016 * 4;            // ~54.8 KB
    cudaFuncSetAttribute(k2_dwom, cudaFuncAttributeMaxDynamicSharedMemorySize, K2_SMEM);
    cudaFuncSetAttribute(k3_dcn,  cudaFuncAttributeMaxDynamicSharedMemorySize, K3_SMEM);

    k1_valproj<<<NROWS / 128, 256>>>(x, vp_w, vp_b);
    k2_dwom<<<NB * (PB / 64), 256, K2_SMEM>>>(x, dw_w, dw_b, om_w, om_b);
    k3_dcn<<<NB * 512, 256, K3_SMEM>>>(op_w, op_b, bn_g, bn_b, bn_m, bn_v, out);
}